// round 9
// baseline (speedup 1.0000x reference)
#include <cuda_runtime.h>

#define RES 30
#define NI 32
#define NC 32
#define NPTS (NI * NC)        // 1024
#define GRID_PTS (RES * RES)  // 900
#define NTHREADS 480          // 15 warps
#define IBLK 8                // intervals per staging block
#define NBLK (NI / IBLK)
#define LSTRIDE 64            // floats per candidate list (32 cands * 2 floats)
#define TBAND 0.55f           // (py-gy)^2 > TBAND => term is exactly 0 in fp32 ref

// exp(-200*m) == exp2(KS2*m),  KS2 = -200 * log2(e)
#define KS2 (-288.53900817779268f)

typedef unsigned long long ull;

__device__ __forceinline__ ull pk2(float lo, float hi) {
    ull r; asm("mov.b64 %0, {%1, %2};" : "=l"(r) : "f"(lo), "f"(hi)); return r;
}
__device__ __forceinline__ float2 unpk(ull v) {
    float2 r; asm("mov.b64 {%0, %1}, %2;" : "=f"(r.x), "=f"(r.y) : "l"(v)); return r;
}
__device__ __forceinline__ ull fma2(ull a, ull b, ull c) {
    ull r; asm("fma.rn.f32x2 %0, %1, %2, %3;" : "=l"(r) : "l"(a), "l"(b), "l"(c)); return r;
}
__device__ __forceinline__ float ex2f(float x) {
    float r; asm("ex2.approx.ftz.f32 %0, %1;" : "=f"(r) : "f"(x)); return r;
}

// dynamic smem layout (in floats):
//   sxy    [2][1024] float2   : 4096 floats   {x,y} per birth/death point
//   sr     [2][1024] float    : 2048          r = x^2+y^2
//   cq     [30][IBLK][2][64]  : 30720         candidate quads {px0,px1,A0,A1}...
//   axx[30] axy[30] w2s[32] red[60] slohi[4] : 186
//   counts [30][IBLK][2] int  : 480
#define OFF_SR    4096
#define OFF_CQ    6144
#define OFF_AXX   (OFF_CQ + 30 * IBLK * 2 * LSTRIDE)   // 6144 + 30720 = 36864
#define OFF_AXY   (OFF_AXX + 30)
#define OFF_W2S   (OFF_AXY + 30)
#define OFF_RED   (OFF_W2S + 32)
#define OFF_SLOHI (OFF_RED + 60)
#define OFF_CNT   (OFF_SLOHI + 4)
#define SMEM_FLOATS (OFF_CNT + 30 * IBLK * 2)
#define SMEM_BYTES  (SMEM_FLOATS * 4)

__global__ __launch_bounds__(NTHREADS, 1)
void persim_kernel(const float* __restrict__ births,
                   const float* __restrict__ deaths,
                   float* __restrict__ out) {
    extern __shared__ float sm[];
    float2* sxy   = (float2*)sm;            // [bd*1024 + p]
    float*  sr    = sm + OFF_SR;            // [bd*1024 + p]
    float*  cq    = sm + OFF_CQ;
    float*  axx   = sm + OFF_AXX;
    float*  axy   = sm + OFF_AXY;
    float*  w2s   = sm + OFF_W2S;
    float*  red   = sm + OFF_RED;
    float*  slohi = sm + OFF_SLOHI;         // {lox, hix, loy, hiy}
    int*    counts = (int*)(sm + OFF_CNT);  // [(row*IBLK+il)*2+bd]

    const int s   = blockIdx.x;
    const int tid = threadIdx.x;

    const float2* bp = (const float2*)(births + (size_t)s * NPTS * 2);
    const float2* dp = (const float2*)(deaths + (size_t)s * NPTS * 2);

    // ---- Phase 1: stage points, r = x^2+y^2, bbox reduction ----
    float mnx = 1e30f, mxx = -1e30f, mny = 1e30f, mxy = -1e30f;
    for (int p = tid; p < NPTS; p += NTHREADS) {
        float2 b = bp[p];
        float2 d = dp[p];
        sxy[p]        = b;
        sxy[1024 + p] = d;
        sr[p]         = fmaf(b.x, b.x, b.y * b.y);
        sr[1024 + p]  = fmaf(d.x, d.x, d.y * d.y);
        mnx = fminf(mnx, fminf(b.x, d.x));
        mxx = fmaxf(mxx, fmaxf(b.x, d.x));
        mny = fminf(mny, fminf(b.y, d.y));
        mxy = fmaxf(mxy, fmaxf(b.y, d.y));
    }
#pragma unroll
    for (int o = 16; o; o >>= 1) {
        mnx = fminf(mnx, __shfl_xor_sync(0xffffffffu, mnx, o));
        mxx = fmaxf(mxx, __shfl_xor_sync(0xffffffffu, mxx, o));
        mny = fminf(mny, __shfl_xor_sync(0xffffffffu, mny, o));
        mxy = fmaxf(mxy, __shfl_xor_sync(0xffffffffu, mxy, o));
    }
    const int w    = tid >> 5;
    const int lane = tid & 31;
    if (lane == 0) {
        red[w * 4 + 0] = mnx;
        red[w * 4 + 1] = mxx;
        red[w * 4 + 2] = mny;
        red[w * 4 + 3] = mxy;
    }
    __syncthreads();

    if (tid == 0) {
        float a = red[0], b = red[1], c = red[2], d = red[3];
#pragma unroll
        for (int ww = 1; ww < 15; ww++) {
            a = fminf(a, red[ww * 4 + 0]);
            b = fmaxf(b, red[ww * 4 + 1]);
            c = fminf(c, red[ww * 4 + 2]);
            d = fmaxf(d, red[ww * 4 + 3]);
        }
        float mgx = 0.1f * (b - a);
        float mgy = 0.1f * (d - c);
        slohi[0] = a - mgx; slohi[1] = b + mgx;
        slohi[2] = c - mgy; slohi[3] = d + mgy;
    }
    // interval weights (warp 1), overlapped with bbox finalize
    if (tid >= 32 && tid < 64) {
        int i = tid - 32;
        float sum = 0.0f;
#pragma unroll 8
        for (int c = 0; c < NC; c++) {
            float2 b = sxy[i * NC + c];
            float2 d = sxy[1024 + i * NC + c];
            sum += fmaxf(fabsf(d.x - b.x), fabsf(d.y - b.y));
        }
        float wv = sum * (1.0f / NC);
        w2s[i] = wv * wv;
    }
    __syncthreads();

    if (tid < RES) {
        float t = (float)tid * (1.0f / (RES - 1));
        axx[tid] = slohi[0] + t * (slohi[1] - slohi[0]);
        axy[tid] = slohi[2] + t * (slohi[3] - slohi[2]);
    }
    __syncthreads();

    // ---- Phase 2: band-pruned KDE ----
    // Build task (per 8-interval block): tid -> (iy, i_l, bd), 480 tasks.
    const int b_iy = tid >> 4;
    const int b_il = (tid & 15) >> 1;
    const int b_bd = tid & 1;

    // Eval mapping: warp w owns rows {w, 29-w}; lane = ix column (30 of 32 active).
    const bool lane_ok = (lane < RES);
    const int  ix  = lane_ok ? lane : (RES - 1);
    const float gx = axx[ix];
    const ull n2gx2 = pk2(-2.0f * gx, -2.0f * gx);
    const int r0 = w, r1 = 29 - w;
    const float gy0 = axy[r0], gy1 = axy[r1];
    const float kg0 = KS2 * fmaf(gx, gx, gy0 * gy0);
    const float kg1 = KS2 * fmaf(gx, gx, gy1 * gy1);

    float acc0 = 0.0f, acc1 = 0.0f;

    for (int blk = 0; blk < NBLK; blk++) {
        // -- build candidate lists for this 8-interval block --
        {
            const int i    = blk * IBLK + b_il;
            const float gy = axy[b_iy];
            const float n2gy = -2.0f * gy;
            const float2* xy = sxy + b_bd * 1024 + i * NC;
            const float*  rr = sr  + b_bd * 1024 + i * NC;
            const int base = ((b_iy * IBLK + b_il) * 2 + b_bd) * LSTRIDE;
            int cnt = 0;
#pragma unroll 8
            for (int c = 0; c < NC; c++) {
                float2 P = xy[c];
                float  r = rr[c];
                float gap = P.y - gy;
                if (gap * gap <= TBAND) {
                    int q = cnt >> 1, pos = cnt & 1;
                    cq[base + q * 4 + pos]     = P.x;
                    cq[base + q * 4 + 2 + pos] = fmaf(n2gy, P.y, r);
                    cnt++;
                }
            }
            // sentinel-pad to a multiple of 4 candidates (A=1e30 never wins the min)
            int padded = (cnt + 3) & ~3;
            for (int pdx = cnt; pdx < padded; pdx++) {
                int q = pdx >> 1, pos = pdx & 1;
                cq[base + q * 4 + pos]     = 0.0f;
                cq[base + q * 4 + 2 + pos] = 1e30f;
            }
            counts[(b_iy * IBLK + b_il) * 2 + b_bd] = cnt;
        }
        __syncthreads();

        // -- evaluate this block's intervals for both owned rows --
#pragma unroll 1
        for (int rs = 0; rs < 2; rs++) {
            const int   row = rs ? r1 : r0;
            const float kg  = rs ? kg1 : kg0;
            float acc = 0.0f;
#pragma unroll 1
            for (int il = 0; il < IBLK; il++) {
                const int cidx = (row * IBLK + il) * 2;
                const int cb = counts[cidx];
                const int cd = counts[cidx + 1];
                if ((cb == 0) || (cd == 0)) continue;   // warp-uniform

                const float* lb = cq + cidx * LSTRIDE;
                const float* ld = lb + LSTRIDE;

                float minb = 1e30f;
                for (int c = 0; c < cb; c += 4) {
                    ulonglong2 Q0 = *(const ulonglong2*)(lb + c * 2);
                    ulonglong2 Q1 = *(const ulonglong2*)(lb + c * 2 + 4);
                    float2 b0 = unpk(fma2(n2gx2, Q0.x, Q0.y));
                    float2 b1 = unpk(fma2(n2gx2, Q1.x, Q1.y));
                    minb = fminf(minb, fminf(b0.x, b0.y));
                    minb = fminf(minb, fminf(b1.x, b1.y));
                }
                float mind = 1e30f;
                for (int c = 0; c < cd; c += 4) {
                    ulonglong2 Q0 = *(const ulonglong2*)(ld + c * 2);
                    ulonglong2 Q1 = *(const ulonglong2*)(ld + c * 2 + 4);
                    float2 d0 = unpk(fma2(n2gx2, Q0.x, Q0.y));
                    float2 d1 = unpk(fma2(n2gx2, Q1.x, Q1.y));
                    mind = fminf(mind, fminf(d0.x, d0.y));
                    mind = fminf(mind, fminf(d1.x, d1.y));
                }
                float mm  = fmaxf(minb, mind);
                float arg = fmaf(KS2, mm, kg);          // KS2*(g2 + bracket)
                acc = fmaf(w2s[blk * IBLK + il], ex2f(arg), acc);
            }
            if (rs) acc1 += acc; else acc0 += acc;
        }
        __syncthreads();   // before next block overwrites the lists
    }

    if (lane_ok) {
        float* orow = out + (size_t)s * GRID_PTS;
        orow[ix * RES + r0] = acc0;
        orow[ix * RES + r1] = acc1;
    }
}

extern "C" void kernel_launch(void* const* d_in, const int* in_sizes, int n_in,
                              void* d_out, int out_size) {
    const float* births = (const float*)d_in[0];
    const float* deaths = (const float*)d_in[1];
    float* out = (float*)d_out;
    int S = in_sizes[0] / (NPTS * 2);   // 128 for the reference shapes
    cudaFuncSetAttribute(persim_kernel,
                         cudaFuncAttributeMaxDynamicSharedMemorySize, SMEM_BYTES);
    persim_kernel<<<S, NTHREADS, SMEM_BYTES>>>(births, deaths, out);
}

// round 10
// speedup vs baseline: 1.1769x; 1.1769x over previous
#include <cuda_runtime.h>

#define RES 30
#define NI 32
#define NC 32
#define NPTS (NI * NC)        // 1024
#define GRID_PTS (RES * RES)  // 900
#define NTHREADS 960          // 30 warps
#define IBLK 8                // intervals staged per block
#define NBLK (NI / IBLK)
#define LSTRIDE 68            // floats per candidate list (max 64 used + pad)
#define TBAND 0.55f           // (py-gy)^2 > TBAND => term exactly 0 in fp32 ref

// exp(-200*m) == exp2(KS2*m),  KS2 = -200 * log2(e)
#define KS2 (-288.53900817779268f)

typedef unsigned long long ull;

__device__ __forceinline__ ull pk2(float lo, float hi) {
    ull r; asm("mov.b64 %0, {%1, %2};" : "=l"(r) : "f"(lo), "f"(hi)); return r;
}
__device__ __forceinline__ float2 unpk(ull v) {
    float2 r; asm("mov.b64 {%0, %1}, %2;" : "=f"(r.x), "=f"(r.y) : "l"(v)); return r;
}
__device__ __forceinline__ ull fma2(ull a, ull b, ull c) {
    ull r; asm("fma.rn.f32x2 %0, %1, %2, %3;" : "=l"(r) : "l"(a), "l"(b), "l"(c)); return r;
}
__device__ __forceinline__ float ex2f(float x) {
    float r; asm("ex2.approx.ftz.f32 %0, %1;" : "=f"(r) : "f"(x)); return r;
}

// dynamic smem layout (float offsets)
#define OFF_SXY   0                                   // float2[2][1024] = 4096 f
#define OFF_SR    4096                                // float [2][1024] = 2048 f
#define OFF_CQ    6144                                // [30][IBLK][2][LSTRIDE] = 32640 f
#define OFF_AXX   (OFF_CQ + 30 * IBLK * 2 * LSTRIDE)  // 38784
#define OFF_AXY   (OFF_AXX + 30)
#define OFF_W2S   (OFF_AXY + 30)
#define OFF_RED   (OFF_W2S + 32)                      // 30 warps * 4
#define OFF_SLOHI (OFF_RED + 120)
#define OFF_PACC  (OFF_SLOHI + 4)                     // [15][2][32] = 960 f
#define OFF_CNT   (OFF_PACC + 960)                    // int[30*IBLK*2] = 480
#define SMEM_FLOATS (OFF_CNT + 480)
#define SMEM_BYTES  (SMEM_FLOATS * 4)

__global__ __launch_bounds__(NTHREADS, 1)
void persim_kernel(const float* __restrict__ births,
                   const float* __restrict__ deaths,
                   float* __restrict__ out) {
    extern __shared__ float sm[];
    float2* sxy    = (float2*)(sm + OFF_SXY);   // [bd*1024 + p]
    float*  sr     = sm + OFF_SR;
    float*  cq     = sm + OFF_CQ;
    float*  axx    = sm + OFF_AXX;
    float*  axy    = sm + OFF_AXY;
    float*  w2s    = sm + OFF_W2S;
    float*  red    = sm + OFF_RED;
    float*  slohi  = sm + OFF_SLOHI;
    float*  pacc   = sm + OFF_PACC;             // [rp][row01][lane]
    int*    counts = (int*)(sm + OFF_CNT);      // [(iy*IBLK+il)*2+bd]

    const int s   = blockIdx.x;
    const int tid = threadIdx.x;
    const int w    = tid >> 5;
    const int lane = tid & 31;

    const float2* bpg = (const float2*)(births + (size_t)s * NPTS * 2);
    const float2* dpg = (const float2*)(deaths + (size_t)s * NPTS * 2);

    // ---- Phase 1: stage points, r = x^2+y^2, bbox reduction ----
    float mnx = 1e30f, mxx = -1e30f, mny = 1e30f, mxy = -1e30f;
    for (int p = tid; p < NPTS; p += NTHREADS) {
        float2 b = bpg[p];
        float2 d = dpg[p];
        sxy[p]        = b;
        sxy[1024 + p] = d;
        sr[p]         = fmaf(b.x, b.x, b.y * b.y);
        sr[1024 + p]  = fmaf(d.x, d.x, d.y * d.y);
        mnx = fminf(mnx, fminf(b.x, d.x));
        mxx = fmaxf(mxx, fmaxf(b.x, d.x));
        mny = fminf(mny, fminf(b.y, d.y));
        mxy = fmaxf(mxy, fmaxf(b.y, d.y));
    }
#pragma unroll
    for (int o = 16; o; o >>= 1) {
        mnx = fminf(mnx, __shfl_xor_sync(0xffffffffu, mnx, o));
        mxx = fmaxf(mxx, __shfl_xor_sync(0xffffffffu, mxx, o));
        mny = fminf(mny, __shfl_xor_sync(0xffffffffu, mny, o));
        mxy = fmaxf(mxy, __shfl_xor_sync(0xffffffffu, mxy, o));
    }
    if (lane == 0) {
        red[w * 4 + 0] = mnx;
        red[w * 4 + 1] = mxx;
        red[w * 4 + 2] = mny;
        red[w * 4 + 3] = mxy;
    }
    __syncthreads();

    if (tid == 0) {
        float a = red[0], b = red[1], c = red[2], d = red[3];
#pragma unroll
        for (int ww = 1; ww < 30; ww++) {
            a = fminf(a, red[ww * 4 + 0]);
            b = fmaxf(b, red[ww * 4 + 1]);
            c = fminf(c, red[ww * 4 + 2]);
            d = fmaxf(d, red[ww * 4 + 3]);
        }
        float mgx = 0.1f * (b - a);
        float mgy = 0.1f * (d - c);
        slohi[0] = a - mgx; slohi[1] = b + mgx;
        slohi[2] = c - mgy; slohi[3] = d + mgy;
    }
    // interval weights (warp 1)
    if (tid >= 32 && tid < 64) {
        int i = tid - 32;
        float sum = 0.0f;
#pragma unroll 8
        for (int c = 0; c < NC; c++) {
            float2 b = sxy[i * NC + c];
            float2 d = sxy[1024 + i * NC + c];
            sum += fmaxf(fabsf(d.x - b.x), fabsf(d.y - b.y));
        }
        float wv = sum * (1.0f / NC);
        w2s[i] = wv * wv;
    }
    __syncthreads();

    if (tid < RES) {
        float t = (float)tid * (1.0f / (RES - 1));
        axx[tid] = slohi[0] + t * (slohi[1] - slohi[0]);
        axy[tid] = slohi[2] + t * (slohi[3] - slohi[2]);
    }
    __syncthreads();

    // ---- Phase 2: band-pruned KDE, row-per-warp (all loop bounds warp-uniform) --
    // warp w: row pair {rp, 29-rp}, interval half ihalf; lane = grid column.
    const int rp    = w % 15;
    const int ihalf = w / 15;
    const int r0 = rp, r1 = 29 - rp;
    const bool lane_ok = (lane < RES);
    const int  ix = lane_ok ? lane : (RES - 1);
    const float gx = axx[ix];
    const ull n2gx2 = pk2(-2.0f * gx, -2.0f * gx);
    const float gy0 = axy[r0], gy1 = axy[r1];
    const float kg0 = KS2 * fmaf(gx, gx, gy0 * gy0);
    const float kg1 = KS2 * fmaf(gx, gx, gy1 * gy1);

    // build task mapping (tid < 480): (iy, il, bd)
    const int b_iy = tid >> 4;
    const int b_il = (tid >> 1) & 7;
    const int b_bd = tid & 1;

    float acc0 = 0.0f, acc1 = 0.0f;

    for (int blk = 0; blk < NBLK; blk++) {
        // -- build candidate lists {px, A=r-2gy*py} for this 8-interval block --
        if (tid < 480) {
            const int i    = blk * IBLK + b_il;
            const float gy = axy[b_iy];
            const float n2gy = -2.0f * gy;
            const float2* xy = sxy + b_bd * 1024 + i * NC;
            const float*  rr = sr  + b_bd * 1024 + i * NC;
            const int base = ((b_iy * IBLK + b_il) * 2 + b_bd) * LSTRIDE;
            int cnt = 0;
            for (int c = 0; c < NC; c++) {
                float2 P = xy[c];
                float  r = rr[c];
                float gap = P.y - gy;
                if (gap * gap <= TBAND) {
                    int q = cnt >> 1, pos = cnt & 1;
                    cq[base + q * 4 + pos]     = P.x;
                    cq[base + q * 4 + 2 + pos] = fmaf(n2gy, P.y, r);
                    cnt++;
                }
            }
            int padded = (cnt + 3) & ~3;   // sentinel-pad to 2-pair multiple
            for (int pdx = cnt; pdx < padded; pdx++) {
                int q = pdx >> 1, pos = pdx & 1;
                cq[base + q * 4 + pos]     = 0.0f;
                cq[base + q * 4 + 2 + pos] = 1e30f;
            }
            counts[(b_iy * IBLK + b_il) * 2 + b_bd] = cnt;
        }
        __syncthreads();

        // -- evaluate: this warp's 4 intervals x 2 rows --
#pragma unroll
        for (int j = 0; j < 4; j++) {
            const int ilq = ihalf * 4 + j;
            const float wv = w2s[blk * IBLK + ilq];
#pragma unroll
            for (int rs = 0; rs < 2; rs++) {
                const int   row = rs ? r1 : r0;
                const float kg  = rs ? kg1 : kg0;
                const int cidx = (row * IBLK + ilq) * 2;
                const int cb = counts[cidx];
                const int cd = counts[cidx + 1];
                if (cb > 0 && cd > 0) {          // warp-uniform; empty => exact 0
                    const float4* lb = (const float4*)(cq + cidx * LSTRIDE);
                    const float4* ld = lb + (LSTRIDE / 4);
                    const int qb = (cb + 3) >> 2;
                    const int qd = (cd + 3) >> 2;

                    float minb = 1e30f;
                    for (int q = 0; q < qb; q++) {
                        float4 a = lb[2 * q];
                        float4 b = lb[2 * q + 1];
                        float2 m0 = unpk(fma2(n2gx2, pk2(a.x, a.y), pk2(a.z, a.w)));
                        float2 m1 = unpk(fma2(n2gx2, pk2(b.x, b.y), pk2(b.z, b.w)));
                        minb = fminf(minb, fminf(fminf(m0.x, m0.y), fminf(m1.x, m1.y)));
                    }
                    float mind = 1e30f;
                    for (int q = 0; q < qd; q++) {
                        float4 a = ld[2 * q];
                        float4 b = ld[2 * q + 1];
                        float2 m0 = unpk(fma2(n2gx2, pk2(a.x, a.y), pk2(a.z, a.w)));
                        float2 m1 = unpk(fma2(n2gx2, pk2(b.x, b.y), pk2(b.z, b.w)));
                        mind = fminf(mind, fminf(fminf(m0.x, m0.y), fminf(m1.x, m1.y)));
                    }
                    float mm  = fmaxf(minb, mind);
                    float arg = fmaf(KS2, mm, kg);
                    float v   = wv * ex2f(arg);
                    if (rs) acc1 += v; else acc0 += v;
                }
            }
        }
        __syncthreads();   // before next block overwrites lists
    }

    // ---- merge interval halves and store ----
    if (ihalf == 1) {
        pacc[(rp * 2 + 0) * 32 + lane] = acc0;
        pacc[(rp * 2 + 1) * 32 + lane] = acc1;
    }
    __syncthreads();
    if (ihalf == 0 && lane_ok) {
        float* orow = out + (size_t)s * GRID_PTS;
        orow[ix * RES + r0] = acc0 + pacc[(rp * 2 + 0) * 32 + lane];
        orow[ix * RES + r1] = acc1 + pacc[(rp * 2 + 1) * 32 + lane];
    }
}

extern "C" void kernel_launch(void* const* d_in, const int* in_sizes, int n_in,
                              void* d_out, int out_size) {
    const float* births = (const float*)d_in[0];
    const float* deaths = (const float*)d_in[1];
    float* out = (float*)d_out;
    int S = in_sizes[0] / (NPTS * 2);   // 128 for the reference shapes
    cudaFuncSetAttribute(persim_kernel,
                         cudaFuncAttributeMaxDynamicSharedMemorySize, SMEM_BYTES);
    persim_kernel<<<S, NTHREADS, SMEM_BYTES>>>(births, deaths, out);
}

// round 11
// speedup vs baseline: 1.7758x; 1.5089x over previous
#include <cuda_runtime.h>

#define RES 30
#define NI 32
#define NC 32
#define NPTS (NI * NC)        // 1024
#define GRID_PTS (RES * RES)  // 900
#define NTHREADS 960          // 30 warps
#define IBLK 8                // intervals staged per block
#define NBLK (NI / IBLK)
#define PLANE 36              // floats per plane (32 cands + 4 sentinel pad)
#define LSTRIDE 72            // floats per list (px plane + A plane)
#define NLISTS (RES * IBLK * 2)   // 480 lists per block
#define TBAND 0.55f           // (py-gy)^2 > TBAND => term exactly 0 in fp32 ref

// exp(-200*m) == exp2(KS2*m),  KS2 = -200 * log2(e)
#define KS2 (-288.53900817779268f)

typedef unsigned long long ull;

__device__ __forceinline__ ull pk2(float lo, float hi) {
    ull r; asm("mov.b64 %0, {%1, %2};" : "=l"(r) : "f"(lo), "f"(hi)); return r;
}
__device__ __forceinline__ float2 unpk(ull v) {
    float2 r; asm("mov.b64 {%0, %1}, %2;" : "=f"(r.x), "=f"(r.y) : "l"(v)); return r;
}
__device__ __forceinline__ ull fma2(ull a, ull b, ull c) {
    ull r; asm("fma.rn.f32x2 %0, %1, %2, %3;" : "=l"(r) : "l"(a), "l"(b), "l"(c)); return r;
}
__device__ __forceinline__ float ex2f(float x) {
    float r; asm("ex2.approx.ftz.f32 %0, %1;" : "=f"(r) : "f"(x)); return r;
}

// dynamic smem layout (float offsets)
#define OFF_SXY   0                               // float2[2][1024] = 4096 f
#define OFF_CQ    4096                            // [480][LSTRIDE] = 34560 f
#define OFF_AXX   (OFF_CQ + NLISTS * LSTRIDE)     // 38656
#define OFF_AXY   (OFF_AXX + RES)
#define OFF_W2S   (OFF_AXY + RES)
#define OFF_RED   (OFF_W2S + NI)                  // 30 warps * 4
#define OFF_SLOHI (OFF_RED + 120)
#define OFF_PACC  (OFF_SLOHI + 4)                 // [15][2][32] = 960 f
#define OFF_CNT   (OFF_PACC + 960)                // int[480]
#define SMEM_FLOATS (OFF_CNT + NLISTS)
#define SMEM_BYTES  (SMEM_FLOATS * 4)

__global__ __launch_bounds__(NTHREADS, 1)
void persim_kernel(const float* __restrict__ births,
                   const float* __restrict__ deaths,
                   float* __restrict__ out) {
    extern __shared__ float sm[];
    float2* sxy    = (float2*)(sm + OFF_SXY);   // [bd*1024 + p]
    float*  cq     = sm + OFF_CQ;
    float*  axx    = sm + OFF_AXX;
    float*  axy    = sm + OFF_AXY;
    float*  w2s    = sm + OFF_W2S;
    float*  red    = sm + OFF_RED;
    float*  slohi  = sm + OFF_SLOHI;
    float*  pacc   = sm + OFF_PACC;
    int*    counts = (int*)(sm + OFF_CNT);      // [(row*IBLK+il)*2+bd]

    const int s    = blockIdx.x;
    const int tid  = threadIdx.x;
    const int w    = tid >> 5;
    const int lane = tid & 31;

    const float2* bpg = (const float2*)(births + (size_t)s * NPTS * 2);
    const float2* dpg = (const float2*)(deaths + (size_t)s * NPTS * 2);

    // ---- Phase 1: stage points + bbox reduction ----
    float mnx = 1e30f, mxx = -1e30f, mny = 1e30f, mxy = -1e30f;
    for (int p = tid; p < NPTS; p += NTHREADS) {
        float2 b = bpg[p];
        float2 d = dpg[p];
        sxy[p]        = b;
        sxy[1024 + p] = d;
        mnx = fminf(mnx, fminf(b.x, d.x));
        mxx = fmaxf(mxx, fmaxf(b.x, d.x));
        mny = fminf(mny, fminf(b.y, d.y));
        mxy = fmaxf(mxy, fmaxf(b.y, d.y));
    }
#pragma unroll
    for (int o = 16; o; o >>= 1) {
        mnx = fminf(mnx, __shfl_xor_sync(0xffffffffu, mnx, o));
        mxx = fmaxf(mxx, __shfl_xor_sync(0xffffffffu, mxx, o));
        mny = fminf(mny, __shfl_xor_sync(0xffffffffu, mny, o));
        mxy = fmaxf(mxy, __shfl_xor_sync(0xffffffffu, mxy, o));
    }
    if (lane == 0) {
        red[w * 4 + 0] = mnx;
        red[w * 4 + 1] = mxx;
        red[w * 4 + 2] = mny;
        red[w * 4 + 3] = mxy;
    }
    __syncthreads();

    if (tid == 0) {
        float a = red[0], b = red[1], c = red[2], d = red[3];
#pragma unroll
        for (int ww = 1; ww < 30; ww++) {
            a = fminf(a, red[ww * 4 + 0]);
            b = fmaxf(b, red[ww * 4 + 1]);
            c = fminf(c, red[ww * 4 + 2]);
            d = fmaxf(d, red[ww * 4 + 3]);
        }
        float mgx = 0.1f * (b - a);
        float mgy = 0.1f * (d - c);
        slohi[0] = a - mgx; slohi[1] = b + mgx;
        slohi[2] = c - mgy; slohi[3] = d + mgy;
    }
    // interval weights (warp 1)
    if (tid >= 32 && tid < 64) {
        int i = tid - 32;
        float sum = 0.0f;
#pragma unroll 8
        for (int c = 0; c < NC; c++) {
            float2 b = sxy[i * NC + c];
            float2 d = sxy[1024 + i * NC + c];
            sum += fmaxf(fabsf(d.x - b.x), fabsf(d.y - b.y));
        }
        float wv = sum * (1.0f / NC);
        w2s[i] = wv * wv;
    }
    __syncthreads();

    if (tid < RES) {
        float t = (float)tid * (1.0f / (RES - 1));
        axx[tid] = slohi[0] + t * (slohi[1] - slohi[0]);
        axy[tid] = slohi[2] + t * (slohi[3] - slohi[2]);
    }
    __syncthreads();

    // ---- Phase 2: band-pruned KDE ----
    // Build: warp w owns row w; lane = corner index (conflict-free).
    // Eval:  warp w -> row pair {w%15, 29-w%15}, interval half w/15; lane = column.
    const int rp    = w % 15;
    const int ihalf = w / 15;
    const int r0 = rp, r1 = 29 - rp;
    const bool lane_ok = (lane < RES);
    const int  ix = lane_ok ? lane : (RES - 1);
    const float gx = axx[ix];
    const ull n2gx2 = pk2(-2.0f * gx, -2.0f * gx);
    const float gy0 = axy[r0], gy1 = axy[r1];
    const float kg0 = KS2 * fmaf(gx, gx, gy0 * gy0);
    const float kg1 = KS2 * fmaf(gx, gx, gy1 * gy1);

    const float gyw  = axy[w];       // build row's gy
    const float t2gy = 2.0f * gyw;

    float acc0 = 0.0f, acc1 = 0.0f;

    for (int blk = 0; blk < NBLK; blk++) {
        // -- build: 16 lists per warp (il 0..7 x bd 0..1), ballot compaction --
#pragma unroll 1
        for (int j = 0; j < 16; j++) {
            const int il = j >> 1;
            const int bd = j & 1;
            const int i  = blk * IBLK + il;
            float2 P = sxy[bd * 1024 + i * NC + lane];
            float gap = P.y - gyw;
            bool keep = (gap * gap <= TBAND);
            // A = px^2 + py^2 - 2*gy*py = fma(px,px, py*(py-2gy))
            float A = fmaf(P.x, P.x, P.y * (P.y - t2gy));
            unsigned mask = __ballot_sync(0xffffffffu, keep);
            int cnt = __popc(mask);
            int pfx = __popc(mask & ((1u << lane) - 1u));
            float* base = cq + ((w * IBLK + il) * 2 + bd) * LSTRIDE;
            if (lane < 4) {                    // sentinel pad at cnt..cnt+3
                base[cnt + lane]         = 0.0f;
                base[PLANE + cnt + lane] = 1e30f;
            }
            if (keep) {
                base[pfx]         = P.x;
                base[PLANE + pfx] = A;
            }
            if (lane == 0) counts[(w * IBLK + il) * 2 + bd] = cnt;
        }
        __syncthreads();

        // -- eval: 4 intervals x 2 rows, branchless (empty list => term 0) --
        int4 c0a = *(const int4*)&counts[r0 * 16 + ihalf * 8];      // il j=0,1 (b,d)
        int4 c0b = *(const int4*)&counts[r0 * 16 + ihalf * 8 + 4];  // il j=2,3
        int4 c1a = *(const int4*)&counts[r1 * 16 + ihalf * 8];
        int4 c1b = *(const int4*)&counts[r1 * 16 + ihalf * 8 + 4];
        const int cnts[16] = {c0a.x, c0a.y, c0a.z, c0a.w, c0b.x, c0b.y, c0b.z, c0b.w,
                              c1a.x, c1a.y, c1a.z, c1a.w, c1b.x, c1b.y, c1b.z, c1b.w};

#pragma unroll 1
        for (int rs = 0; rs < 2; rs++) {
            const int   row = rs ? r1 : r0;
            const float kg  = rs ? kg1 : kg0;
            float accl = 0.0f;
#pragma unroll
            for (int j = 0; j < 4; j++) {
                const int ilq = ihalf * 4 + j;
                const int qb = (cnts[rs * 8 + j * 2 + 0] + 3) >> 2;
                const int qd = (cnts[rs * 8 + j * 2 + 1] + 3) >> 2;
                const float* lb = cq + ((row * IBLK + ilq) * 2 + 0) * LSTRIDE;
                const float* ld = lb + LSTRIDE;

                float minb = 1e30f;
                for (int q = 0; q < qb; q++) {
                    ulonglong2 PX = *(const ulonglong2*)(lb + 4 * q);
                    ulonglong2 AA = *(const ulonglong2*)(lb + PLANE + 4 * q);
                    float2 m0 = unpk(fma2(n2gx2, PX.x, AA.x));
                    float2 m1 = unpk(fma2(n2gx2, PX.y, AA.y));
                    minb = fminf(minb, fminf(fminf(m0.x, m0.y), fminf(m1.x, m1.y)));
                }
                float mind = 1e30f;
                for (int q = 0; q < qd; q++) {
                    ulonglong2 PX = *(const ulonglong2*)(ld + 4 * q);
                    ulonglong2 AA = *(const ulonglong2*)(ld + PLANE + 4 * q);
                    float2 m0 = unpk(fma2(n2gx2, PX.x, AA.x));
                    float2 m1 = unpk(fma2(n2gx2, PX.y, AA.y));
                    mind = fminf(mind, fminf(fminf(m0.x, m0.y), fminf(m1.x, m1.y)));
                }
                float mm  = fmaxf(minb, mind);            // empty => 1e30 => ex2 -> 0
                float arg = fmaf(KS2, mm, kg);
                accl = fmaf(w2s[blk * IBLK + ilq], ex2f(arg), accl);
            }
            if (rs) acc1 += accl; else acc0 += accl;
        }
        __syncthreads();   // before next block overwrites lists
    }

    // ---- merge interval halves and store ----
    if (ihalf == 1) {
        pacc[(rp * 2 + 0) * 32 + lane] = acc0;
        pacc[(rp * 2 + 1) * 32 + lane] = acc1;
    }
    __syncthreads();
    if (ihalf == 0 && lane_ok) {
        float* orow = out + (size_t)s * GRID_PTS;
        orow[ix * RES + r0] = acc0 + pacc[(rp * 2 + 0) * 32 + lane];
        orow[ix * RES + r1] = acc1 + pacc[(rp * 2 + 1) * 32 + lane];
    }
}

extern "C" void kernel_launch(void* const* d_in, const int* in_sizes, int n_in,
                              void* d_out, int out_size) {
    const float* births = (const float*)d_in[0];
    const float* deaths = (const float*)d_in[1];
    float* out = (float*)d_out;
    int S = in_sizes[0] / (NPTS * 2);   // 128 for the reference shapes
    cudaFuncSetAttribute(persim_kernel,
                         cudaFuncAttributeMaxDynamicSharedMemorySize, SMEM_BYTES);
    persim_kernel<<<S, NTHREADS, SMEM_BYTES>>>(births, deaths, out);
}

// round 12
// speedup vs baseline: 2.5724x; 1.4486x over previous
#include <cuda_runtime.h>

#define RES 30
#define NI 32
#define NC 32
#define NPTS (NI * NC)        // 1024
#define GRID_PTS (RES * RES)  // 900
#define NTHREADS 512
#define DELTA 0.74161984871f  // sqrt(0.55); (py-gy)^2 > 0.55 => term exactly 0 in fp32

// exp(-200*m) == exp2(KS2*m),  KS2 = -200 * log2(e)
#define KS2 (-288.53900817779268f)

typedef unsigned long long ull;

__device__ __forceinline__ ull pk2(float lo, float hi) {
    ull r; asm("mov.b64 %0, {%1, %2};" : "=l"(r) : "f"(lo), "f"(hi)); return r;
}
__device__ __forceinline__ float2 unpk(ull v) {
    float2 r; asm("mov.b64 {%0, %1}, %2;" : "=f"(r.x), "=f"(r.y) : "l"(v)); return r;
}
__device__ __forceinline__ ull fma2(ull a, ull b, ull c) {
    ull r; asm("fma.rn.f32x2 %0, %1, %2, %3;" : "=l"(r) : "l"(a), "l"(b), "l"(c)); return r;
}
__device__ __forceinline__ float ex2f(float x) {
    float r; asm("ex2.approx.ftz.f32 %0, %1;" : "=f"(r) : "f"(x)); return r;
}

// dynamic smem layout (float offsets)
#define OFF_SXY   0          // float2[2][1024] = 4096 f
#define OFF_QF    4096       // [64 lists][16 quads][4] {py0,py1,r0,r1} = 4096 f
#define OFF_XF    8192       // [64 lists][32] px sorted = 2048 f
#define OFF_BND   10240      // int[64][30] (qlo | qhi<<16) = 1920
#define OFF_AXX   12160      // 30
#define OFF_AXY   12190      // 30
#define OFF_W2S   12220      // 32
#define OFF_RED   12252      // 16 warps * 4
#define OFF_SLOHI 12316      // 4
#define OFF_PACC  12320      // [3][8][120] = 2880
#define SMEM_FLOATS 15200
#define SMEM_BYTES  (SMEM_FLOATS * 4)

#define FULL 0xffffffffu

__global__ __launch_bounds__(NTHREADS, 1)
void persim_kernel(const float* __restrict__ births,
                   const float* __restrict__ deaths,
                   float* __restrict__ out) {
    extern __shared__ float sm[];
    float2* sxy   = (float2*)(sm + OFF_SXY);
    float*  qf    = sm + OFF_QF;
    float*  xf    = sm + OFF_XF;
    int*    bnd   = (int*)(sm + OFF_BND);
    float*  axx   = sm + OFF_AXX;
    float*  axy   = sm + OFF_AXY;
    float*  w2s   = sm + OFF_W2S;
    float*  red   = sm + OFF_RED;
    float*  slohi = sm + OFF_SLOHI;
    float*  pacc  = sm + OFF_PACC;

    const int s    = blockIdx.x;
    const int tid  = threadIdx.x;
    const int w    = tid >> 5;
    const int lane = tid & 31;

    const float2* bpg = (const float2*)(births + (size_t)s * NPTS * 2);
    const float2* dpg = (const float2*)(deaths + (size_t)s * NPTS * 2);

    // ---- Phase 1: stage points + bbox ----
    float mnx = 1e30f, mxx = -1e30f, mny = 1e30f, mxy = -1e30f;
    for (int p = tid; p < NPTS; p += NTHREADS) {
        float2 b = bpg[p];
        float2 d = dpg[p];
        sxy[p]        = b;
        sxy[1024 + p] = d;
        mnx = fminf(mnx, fminf(b.x, d.x));
        mxx = fmaxf(mxx, fmaxf(b.x, d.x));
        mny = fminf(mny, fminf(b.y, d.y));
        mxy = fmaxf(mxy, fmaxf(b.y, d.y));
    }
#pragma unroll
    for (int o = 16; o; o >>= 1) {
        mnx = fminf(mnx, __shfl_xor_sync(FULL, mnx, o));
        mxx = fmaxf(mxx, __shfl_xor_sync(FULL, mxx, o));
        mny = fminf(mny, __shfl_xor_sync(FULL, mny, o));
        mxy = fmaxf(mxy, __shfl_xor_sync(FULL, mxy, o));
    }
    if (lane == 0) {
        red[w * 4 + 0] = mnx;
        red[w * 4 + 1] = mxx;
        red[w * 4 + 2] = mny;
        red[w * 4 + 3] = mxy;
    }
    __syncthreads();

    if (tid == 0) {
        float a = red[0], b = red[1], c = red[2], d = red[3];
#pragma unroll
        for (int ww = 1; ww < 16; ww++) {
            a = fminf(a, red[ww * 4 + 0]);
            b = fmaxf(b, red[ww * 4 + 1]);
            c = fminf(c, red[ww * 4 + 2]);
            d = fmaxf(d, red[ww * 4 + 3]);
        }
        float mgx = 0.1f * (b - a);
        float mgy = 0.1f * (d - c);
        slohi[0] = a - mgx; slohi[1] = b + mgx;
        slohi[2] = c - mgy; slohi[3] = d + mgy;
    }
    // interval weights (warp 1)
    if (tid >= 32 && tid < 64) {
        int i = tid - 32;
        float sum = 0.0f;
#pragma unroll 8
        for (int c = 0; c < NC; c++) {
            float2 b = sxy[i * NC + c];
            float2 d = sxy[1024 + i * NC + c];
            sum += fmaxf(fabsf(d.x - b.x), fabsf(d.y - b.y));
        }
        float wv = sum * (1.0f / NC);
        w2s[i] = wv * wv;
    }
    __syncthreads();

    if (tid < RES) {
        float t = (float)tid * (1.0f / (RES - 1));
        axx[tid] = slohi[0] + t * (slohi[1] - slohi[0]);
        axy[tid] = slohi[2] + t * (slohi[3] - slohi[2]);
    }
    __syncthreads();

    // ---- Phase 2: sort each (interval,stream) list by py once; window bounds --
    for (int L = w; L < 64; L += 16) {
        const int i  = L >> 1;
        const int bd = L & 1;
        float2 P = sxy[bd * 1024 + i * NC + lane];
        float key = P.y;
        float px  = P.x;
        float rr  = fmaf(P.x, P.x, P.y * P.y);

        // bitonic sort ascending by key (payload px, rr)
#pragma unroll
        for (int k2 = 2; k2 <= 32; k2 <<= 1) {
#pragma unroll
            for (int j = k2 >> 1; j; j >>= 1) {
                float ok  = __shfl_xor_sync(FULL, key, j);
                float opx = __shfl_xor_sync(FULL, px, j);
                float orr = __shfl_xor_sync(FULL, rr, j);
                bool takeMax   = (((lane & j) != 0) == ((lane & k2) == 0));
                bool takeOther = takeMax ? (ok > key) : (ok < key);
                if (takeOther) { key = ok; px = opx; rr = orr; }
            }
        }

        // quad planes: {py0,py1,r0,r1}; px contiguous in sorted order
        int q = lane >> 1, pos = lane & 1;
        qf[L * 64 + q * 4 + pos]     = key;
        qf[L * 64 + q * 4 + 2 + pos] = rr;
        xf[L * 32 + lane]            = px;

        // per-row window via shfl binary search (all lanes participate in shfl)
        float klo = ((lane < RES) ? axy[lane] : 0.0f) - DELTA;
        float khi = klo + 2.0f * DELTA;
        int lo = 0, hi = 0;
#pragma unroll
        for (int st = 16; st; st >>= 1) {
            float v1 = __shfl_sync(FULL, key, lo + st - 1);
            if (v1 < klo) lo += st;
            float v2 = __shfl_sync(FULL, key, hi + st - 1);
            if (v2 <= khi) hi += st;
        }
        if (lane < RES) {
            int qlo = lo >> 1;              // outward rounding: supersets are exact
            int qhi = (hi + 1) >> 1;
            bnd[L * 30 + lane] = qlo | (qhi << 16);
        }
    }
    __syncthreads();

    // ---- Phase 3: eval (no barriers). quarter = 8 intervals; thread = row x 8 cols.
    const int quarter = tid >> 7;
    const int t       = tid & 127;
    const bool act    = (t < 120);
    const int iy      = act ? (t >> 2) : 0;
    const int chunk   = t & 3;

    const float gy  = axy[iy];
    const ull n2gy2 = pk2(-2.0f * gy, -2.0f * gy);

    ull   n2gx2[8];
    float kg[8];
#pragma unroll
    for (int k = 0; k < 8; k++) {
        int col = chunk + 4 * k;
        float gx = (col < RES) ? axx[col] : 0.0f;
        n2gx2[k] = pk2(-2.0f * gx, -2.0f * gx);
        kg[k]    = KS2 * fmaf(gx, gx, gy * gy);
    }

    float acc[8];
#pragma unroll
    for (int k = 0; k < 8; k++) acc[k] = 0.0f;

#pragma unroll 1
    for (int ii = 0; ii < 8; ii++) {
        const int i  = quarter * 8 + ii;
        const int Lb = 2 * i, Ld = 2 * i + 1;
        const int wb = bnd[Lb * 30 + iy];
        const int wd = bnd[Ld * 30 + iy];

        float minb[8], mind[8];
#pragma unroll
        for (int k = 0; k < 8; k++) { minb[k] = 1e30f; mind[k] = 1e30f; }

        {
            const float* qp = qf + Lb * 64;
            const float* xp = xf + Lb * 32;
            const int qhi = wb >> 16;
            for (int q = wb & 0xffff; q < qhi; q++) {
                float4 Y = *(const float4*)(qp + 4 * q);   // {py0,py1,r0,r1}
                float2 X = *(const float2*)(xp + 2 * q);   // {px0,px1}
                ull T2 = fma2(n2gy2, pk2(Y.x, Y.y), pk2(Y.z, Y.w));
                ull XX = pk2(X.x, X.y);
#pragma unroll
                for (int k = 0; k < 8; k++) {
                    float2 m = unpk(fma2(n2gx2[k], XX, T2));
                    minb[k] = fminf(minb[k], fminf(m.x, m.y));
                }
            }
        }
        {
            const float* qp = qf + Ld * 64;
            const float* xp = xf + Ld * 32;
            const int qhi = wd >> 16;
            for (int q = wd & 0xffff; q < qhi; q++) {
                float4 Y = *(const float4*)(qp + 4 * q);
                float2 X = *(const float2*)(xp + 2 * q);
                ull T2 = fma2(n2gy2, pk2(Y.x, Y.y), pk2(Y.z, Y.w));
                ull XX = pk2(X.x, X.y);
#pragma unroll
                for (int k = 0; k < 8; k++) {
                    float2 m = unpk(fma2(n2gx2[k], XX, T2));
                    mind[k] = fminf(mind[k], fminf(m.x, m.y));
                }
            }
        }

        const float wv = w2s[i];
#pragma unroll
        for (int k = 0; k < 8; k++) {
            float mm  = fmaxf(minb[k], mind[k]);   // empty window => 1e30 => ex2 -> 0
            float arg = fmaf(KS2, mm, kg[k]);
            acc[k] = fmaf(wv, ex2f(arg), acc[k]);
        }
    }

    // ---- merge quarters and store ----
    if (quarter != 0 && act) {
#pragma unroll
        for (int k = 0; k < 8; k++)
            pacc[(quarter - 1) * 960 + k * 120 + t] = acc[k];
    }
    __syncthreads();
    if (quarter == 0 && act) {
        float* orow = out + (size_t)s * GRID_PTS;
#pragma unroll
        for (int k = 0; k < 8; k++) {
            int col = chunk + 4 * k;
            if (col < RES) {
                float v = acc[k] + pacc[0 * 960 + k * 120 + t]
                                 + pacc[1 * 960 + k * 120 + t]
                                 + pacc[2 * 960 + k * 120 + t];
                orow[col * RES + iy] = v;
            }
        }
    }
}

extern "C" void kernel_launch(void* const* d_in, const int* in_sizes, int n_in,
                              void* d_out, int out_size) {
    const float* births = (const float*)d_in[0];
    const float* deaths = (const float*)d_in[1];
    float* out = (float*)d_out;
    int S = in_sizes[0] / (NPTS * 2);   // 128 for the reference shapes
    cudaFuncSetAttribute(persim_kernel,
                         cudaFuncAttributeMaxDynamicSharedMemorySize, SMEM_BYTES);
    persim_kernel<<<S, NTHREADS, SMEM_BYTES>>>(births, deaths, out);
}

// round 14
// speedup vs baseline: 3.2430x; 1.2607x over previous
#include <cuda_runtime.h>

#define RES 30
#define NI 32
#define NC 32
#define NPTS (NI * NC)        // 1024
#define GRID_PTS (RES * RES)  // 900
#define NTHREADS 960          // 30 warps
#define SETSZ 240             // 30 rows x 8 chunks
#define DELTA 0.74161984871f  // sqrt(0.55); (py-gy)^2 > 0.55 => term exactly 0 in fp32

// exp(-200*m) == exp2(KS2*m),  KS2 = -200 * log2(e)
#define KS2 (-288.53900817779268f)

typedef unsigned long long ull;

__device__ __forceinline__ ull pk2(float lo, float hi) {
    ull r; asm("mov.b64 %0, {%1, %2};" : "=l"(r) : "f"(lo), "f"(hi)); return r;
}
__device__ __forceinline__ float2 unpk(ull v) {
    float2 r; asm("mov.b64 {%0, %1}, %2;" : "=f"(r.x), "=f"(r.y) : "l"(v)); return r;
}
__device__ __forceinline__ ull fma2(ull a, ull b, ull c) {
    ull r; asm("fma.rn.f32x2 %0, %1, %2, %3;" : "=l"(r) : "l"(a), "l"(b), "l"(c)); return r;
}
__device__ __forceinline__ float ex2f(float x) {
    float r; asm("ex2.approx.ftz.f32 %0, %1;" : "=f"(r) : "f"(x)); return r;
}

// dynamic smem layout (float offsets)
#define OFF_SXY   0          // float2[2][1024] = 4096 f
#define OFF_QF    4096       // [64 lists][16 quads][4] {py0,py1,r0,r1} = 4096 f
#define OFF_XF    8192       // [64 lists][32] px sorted = 2048 f
#define OFF_BND   10240      // int[64][30] (qlo | qhi<<16) = 1920
#define OFF_AXX   12160      // 30
#define OFF_AXY   12190      // 30
#define OFF_W2S   12220      // 32
#define OFF_RED   12252      // 30 warps * 4 = 120
#define OFF_SLOHI 12372      // 4
#define OFF_PACC  12376      // [3][4][240] = 2880
#define SMEM_FLOATS 15256
#define SMEM_BYTES  (SMEM_FLOATS * 4)

#define FULL 0xffffffffu

__global__ __launch_bounds__(NTHREADS, 1)
void persim_kernel(const float* __restrict__ births,
                   const float* __restrict__ deaths,
                   float* __restrict__ out) {
    extern __shared__ float sm[];
    float2* sxy   = (float2*)(sm + OFF_SXY);
    float*  qf    = sm + OFF_QF;
    float*  xf    = sm + OFF_XF;
    int*    bnd   = (int*)(sm + OFF_BND);
    float*  axx   = sm + OFF_AXX;
    float*  axy   = sm + OFF_AXY;
    float*  w2s   = sm + OFF_W2S;
    float*  red   = sm + OFF_RED;
    float*  slohi = sm + OFF_SLOHI;
    float*  pacc  = sm + OFF_PACC;

    const int s    = blockIdx.x;
    const int tid  = threadIdx.x;
    const int w    = tid >> 5;
    const int lane = tid & 31;

    const float2* bpg = (const float2*)(births + (size_t)s * NPTS * 2);
    const float2* dpg = (const float2*)(deaths + (size_t)s * NPTS * 2);

    // ---- Phase 1: stage points + bbox ----
    float mnx = 1e30f, mxx = -1e30f, mny = 1e30f, mxy = -1e30f;
    for (int p = tid; p < NPTS; p += NTHREADS) {
        float2 b = bpg[p];
        float2 d = dpg[p];
        sxy[p]        = b;
        sxy[1024 + p] = d;
        mnx = fminf(mnx, fminf(b.x, d.x));
        mxx = fmaxf(mxx, fmaxf(b.x, d.x));
        mny = fminf(mny, fminf(b.y, d.y));
        mxy = fmaxf(mxy, fmaxf(b.y, d.y));
    }
#pragma unroll
    for (int o = 16; o; o >>= 1) {
        mnx = fminf(mnx, __shfl_xor_sync(FULL, mnx, o));
        mxx = fmaxf(mxx, __shfl_xor_sync(FULL, mxx, o));
        mny = fminf(mny, __shfl_xor_sync(FULL, mny, o));
        mxy = fmaxf(mxy, __shfl_xor_sync(FULL, mxy, o));
    }
    if (lane == 0) {
        red[w * 4 + 0] = mnx;
        red[w * 4 + 1] = mxx;
        red[w * 4 + 2] = mny;
        red[w * 4 + 3] = mxy;
    }
    __syncthreads();

    if (tid == 0) {
        float a = red[0], b = red[1], c = red[2], d = red[3];
#pragma unroll
        for (int ww = 1; ww < 30; ww++) {
            a = fminf(a, red[ww * 4 + 0]);
            b = fmaxf(b, red[ww * 4 + 1]);
            c = fminf(c, red[ww * 4 + 2]);
            d = fmaxf(d, red[ww * 4 + 3]);
        }
        float mgx = 0.1f * (b - a);
        float mgy = 0.1f * (d - c);
        slohi[0] = a - mgx; slohi[1] = b + mgx;
        slohi[2] = c - mgy; slohi[3] = d + mgy;
    }
    // interval weights (warp 1)
    if (tid >= 32 && tid < 64) {
        int i = tid - 32;
        float sum = 0.0f;
#pragma unroll 8
        for (int c = 0; c < NC; c++) {
            float2 b = sxy[i * NC + c];
            float2 d = sxy[1024 + i * NC + c];
            sum += fmaxf(fabsf(d.x - b.x), fabsf(d.y - b.y));
        }
        float wv = sum * (1.0f / NC);
        w2s[i] = wv * wv;
    }
    __syncthreads();

    if (tid < RES) {
        float t = (float)tid * (1.0f / (RES - 1));
        axx[tid] = slohi[0] + t * (slohi[1] - slohi[0]);
        axy[tid] = slohi[2] + t * (slohi[3] - slohi[2]);
    }
    __syncthreads();

    // ---- Phase 2: sort each (interval,stream) list by py once; window bounds --
    for (int L = w; L < 64; L += 30) {
        const int i  = L >> 1;
        const int bd = L & 1;
        float2 P = sxy[bd * 1024 + i * NC + lane];
        float key = P.y;
        float px  = P.x;
        float rr  = fmaf(P.x, P.x, P.y * P.y);

        // bitonic sort ascending by key (payload px, rr)
#pragma unroll
        for (int k2 = 2; k2 <= 32; k2 <<= 1) {
#pragma unroll
            for (int j = k2 >> 1; j; j >>= 1) {
                float ok  = __shfl_xor_sync(FULL, key, j);
                float opx = __shfl_xor_sync(FULL, px, j);
                float orr = __shfl_xor_sync(FULL, rr, j);
                bool takeMax   = (((lane & j) != 0) == ((lane & k2) == 0));
                bool takeOther = takeMax ? (ok > key) : (ok < key);
                if (takeOther) { key = ok; px = opx; rr = orr; }
            }
        }

        // quad planes: {py0,py1,r0,r1}; px contiguous in sorted order
        int q = lane >> 1, pos = lane & 1;
        qf[L * 64 + q * 4 + pos]     = key;
        qf[L * 64 + q * 4 + 2 + pos] = rr;
        xf[L * 32 + lane]            = px;

        // per-row window via shfl binary search (all lanes participate in shfl)
        float klo = ((lane < RES) ? axy[lane] : 0.0f) - DELTA;
        float khi = klo + 2.0f * DELTA;
        int lo = 0, hi = 0;
#pragma unroll
        for (int st = 16; st; st >>= 1) {
            float v1 = __shfl_sync(FULL, key, lo + st - 1);
            if (v1 < klo) lo += st;
            float v2 = __shfl_sync(FULL, key, hi + st - 1);
            if (v2 <= khi) hi += st;
        }
        if (lane < RES) {
            int qlo = lo >> 1;              // outward rounding: supersets are exact
            int qhi = (hi + 1) >> 1;
            bnd[L * 30 + lane] = qlo | (qhi << 16);
        }
    }
    __syncthreads();

    // ---- Phase 3: eval (no barriers). 4 sets x 240 threads; set = 8 intervals.
    // thread: iy = t>>3 (row), chunk = t&7, columns chunk + 8k (k<4).
    // Warp spans 4 rows -> small intra-warp window divergence.
    const int set = tid / SETSZ;
    const int t   = tid % SETSZ;
    const int iy    = t >> 3;
    const int chunk = t & 7;

    const float gy  = axy[iy];
    const ull n2gy2 = pk2(-2.0f * gy, -2.0f * gy);

    ull   n2gx2[4];
    float kg[4];
#pragma unroll
    for (int k = 0; k < 4; k++) {
        int col = chunk + 8 * k;
        float gx = (col < RES) ? axx[col] : 0.0f;
        n2gx2[k] = pk2(-2.0f * gx, -2.0f * gx);
        kg[k]    = KS2 * fmaf(gx, gx, gy * gy);
    }

    float acc[4];
#pragma unroll
    for (int k = 0; k < 4; k++) acc[k] = 0.0f;

#pragma unroll 1
    for (int ii = 0; ii < 8; ii++) {
        const int i  = set * 8 + ii;
        const int Lb = 2 * i, Ld = 2 * i + 1;
        const int wb = bnd[Lb * 30 + iy];
        const int wd = bnd[Ld * 30 + iy];

        float minb[4], mind[4];
#pragma unroll
        for (int k = 0; k < 4; k++) { minb[k] = 1e30f; mind[k] = 1e30f; }

        {
            const float* qp = qf + Lb * 64;
            const float* xp = xf + Lb * 32;
            const int qhi = wb >> 16;
            for (int q = wb & 0xffff; q < qhi; q++) {
                float4 Y = *(const float4*)(qp + 4 * q);   // {py0,py1,r0,r1}
                float2 X = *(const float2*)(xp + 2 * q);   // {px0,px1}
                ull T2 = fma2(n2gy2, pk2(Y.x, Y.y), pk2(Y.z, Y.w));
                ull XX = pk2(X.x, X.y);
#pragma unroll
                for (int k = 0; k < 4; k++) {
                    float2 m = unpk(fma2(n2gx2[k], XX, T2));
                    minb[k] = fminf(minb[k], fminf(m.x, m.y));
                }
            }
        }
        {
            const float* qp = qf + Ld * 64;
            const float* xp = xf + Ld * 32;
            const int qhi = wd >> 16;
            for (int q = wd & 0xffff; q < qhi; q++) {
                float4 Y = *(const float4*)(qp + 4 * q);
                float2 X = *(const float2*)(xp + 2 * q);
                ull T2 = fma2(n2gy2, pk2(Y.x, Y.y), pk2(Y.z, Y.w));
                ull XX = pk2(X.x, X.y);
#pragma unroll
                for (int k = 0; k < 4; k++) {
                    float2 m = unpk(fma2(n2gx2[k], XX, T2));
                    mind[k] = fminf(mind[k], fminf(m.x, m.y));
                }
            }
        }

        const float wv = w2s[i];
#pragma unroll
        for (int k = 0; k < 4; k++) {
            float mm  = fmaxf(minb[k], mind[k]);   // empty window => 1e30 => ex2 -> 0
            float arg = fmaf(KS2, mm, kg[k]);
            acc[k] = fmaf(wv, ex2f(arg), acc[k]);
        }
    }

    // ---- merge sets and store ----
    if (set != 0) {
#pragma unroll
        for (int k = 0; k < 4; k++)
            pacc[(set - 1) * 960 + k * SETSZ + t] = acc[k];
    }
    __syncthreads();
    if (set == 0) {
        float* orow = out + (size_t)s * GRID_PTS;
#pragma unroll
        for (int k = 0; k < 4; k++) {
            int col = chunk + 8 * k;
            if (col < RES) {
                float v = acc[k] + pacc[0 * 960 + k * SETSZ + t]
                                 + pacc[1 * 960 + k * SETSZ + t]
                                 + pacc[2 * 960 + k * SETSZ + t];
                orow[col * RES + iy] = v;
            }
        }
    }
}

extern "C" void kernel_launch(void* const* d_in, const int* in_sizes, int n_in,
                              void* d_out, int out_size) {
    const float* births = (const float*)d_in[0];
    const float* deaths = (const float*)d_in[1];
    float* out = (float*)d_out;
    int S = in_sizes[0] / (NPTS * 2);   // 128 for the reference shapes
    cudaFuncSetAttribute(persim_kernel,
                         cudaFuncAttributeMaxDynamicSharedMemorySize, SMEM_BYTES);
    persim_kernel<<<S, NTHREADS, SMEM_BYTES>>>(births, deaths, out);
}

// round 17
// speedup vs baseline: 3.3567x; 1.0351x over previous
#include <cuda_runtime.h>

#define RES 30
#define NI 32
#define NC 32
#define NPTS (NI * NC)        // 1024
#define GRID_PTS (RES * RES)  // 900
#define NTHREADS 960          // 30 warps
#define SETSZ 240             // 30 rows x 8 chunks
#define DELTA 0.74161984871f  // sqrt(0.55); (py-gy)^2 > 0.55 => term exactly 0 in fp32

// exp(-200*m) == exp2(KS2*m),  KS2 = -200 * log2(e)
#define KS2 (-288.53900817779268f)

typedef unsigned long long ull;

__device__ __forceinline__ ull pk2(float lo, float hi) {
    ull r; asm("mov.b64 %0, {%1, %2};" : "=l"(r) : "f"(lo), "f"(hi)); return r;
}
__device__ __forceinline__ float2 unpk(ull v) {
    float2 r; asm("mov.b64 {%0, %1}, %2;" : "=f"(r.x), "=f"(r.y) : "l"(v)); return r;
}
__device__ __forceinline__ ull fma2(ull a, ull b, ull c) {
    ull r; asm("fma.rn.f32x2 %0, %1, %2, %3;" : "=l"(r) : "l"(a), "l"(b), "l"(c)); return r;
}
__device__ __forceinline__ float ex2f(float x) {
    float r; asm("ex2.approx.ftz.f32 %0, %1;" : "=f"(r) : "f"(x)); return r;
}

// dynamic smem layout (float offsets)
#define OFF_SXY   0          // float2[2][1024] = 4096 f
#define OFF_QF    4096       // [64 lists][16 quads][4] {py0,py1,r0,r1} = 4096 f
#define OFF_XF    8192       // [64 lists][32] px sorted = 2048 f
#define OFF_BND   10240      // int[64][30] (qlo | qhi<<16), even-aligned = 1920
#define OFF_AXX   12160      // 30
#define OFF_AXY   12190      // 30
#define OFF_W2S   12220      // 32
#define OFF_RED   12252      // 30 warps * 4 = 120
#define OFF_SLOHI 12372      // 4
#define OFF_PACC  12376      // [3][4][240] = 2880
#define SMEM_FLOATS 15256
#define SMEM_BYTES  (SMEM_FLOATS * 4)

#define FULL 0xffffffffu

__global__ __launch_bounds__(NTHREADS, 1)
void persim_kernel(const float* __restrict__ births,
                   const float* __restrict__ deaths,
                   float* __restrict__ out) {
    extern __shared__ float sm[];
    float2* sxy   = (float2*)(sm + OFF_SXY);
    float*  qf    = sm + OFF_QF;
    float*  xf    = sm + OFF_XF;
    int*    bnd   = (int*)(sm + OFF_BND);
    float*  axx   = sm + OFF_AXX;
    float*  axy   = sm + OFF_AXY;
    float*  w2s   = sm + OFF_W2S;
    float*  red   = sm + OFF_RED;
    float*  slohi = sm + OFF_SLOHI;
    float*  pacc  = sm + OFF_PACC;

    const int s    = blockIdx.x;
    const int tid  = threadIdx.x;
    const int w    = tid >> 5;
    const int lane = tid & 31;

    const float2* bpg = (const float2*)(births + (size_t)s * NPTS * 2);
    const float2* dpg = (const float2*)(deaths + (size_t)s * NPTS * 2);

    // ---- Phase 1: stage points + bbox ----
    float mnx = 1e30f, mxx = -1e30f, mny = 1e30f, mxy = -1e30f;
    for (int p = tid; p < NPTS; p += NTHREADS) {
        float2 b = bpg[p];
        float2 d = dpg[p];
        sxy[p]        = b;
        sxy[1024 + p] = d;
        mnx = fminf(mnx, fminf(b.x, d.x));
        mxx = fmaxf(mxx, fmaxf(b.x, d.x));
        mny = fminf(mny, fminf(b.y, d.y));
        mxy = fmaxf(mxy, fmaxf(b.y, d.y));
    }
#pragma unroll
    for (int o = 16; o; o >>= 1) {
        mnx = fminf(mnx, __shfl_xor_sync(FULL, mnx, o));
        mxx = fmaxf(mxx, __shfl_xor_sync(FULL, mxx, o));
        mny = fminf(mny, __shfl_xor_sync(FULL, mny, o));
        mxy = fmaxf(mxy, __shfl_xor_sync(FULL, mxy, o));
    }
    if (lane == 0) {
        red[w * 4 + 0] = mnx;
        red[w * 4 + 1] = mxx;
        red[w * 4 + 2] = mny;
        red[w * 4 + 3] = mxy;
    }
    __syncthreads();

    if (tid == 0) {
        float a = red[0], b = red[1], c = red[2], d = red[3];
#pragma unroll
        for (int ww = 1; ww < 30; ww++) {
            a = fminf(a, red[ww * 4 + 0]);
            b = fmaxf(b, red[ww * 4 + 1]);
            c = fminf(c, red[ww * 4 + 2]);
            d = fmaxf(d, red[ww * 4 + 3]);
        }
        float mgx = 0.1f * (b - a);
        float mgy = 0.1f * (d - c);
        slohi[0] = a - mgx; slohi[1] = b + mgx;
        slohi[2] = c - mgy; slohi[3] = d + mgy;
    }
    // interval weights (warp 1)
    if (tid >= 32 && tid < 64) {
        int i = tid - 32;
        float sum = 0.0f;
#pragma unroll 8
        for (int c = 0; c < NC; c++) {
            float2 b = sxy[i * NC + c];
            float2 d = sxy[1024 + i * NC + c];
            sum += fmaxf(fabsf(d.x - b.x), fabsf(d.y - b.y));
        }
        float wv = sum * (1.0f / NC);
        w2s[i] = wv * wv;
    }
    __syncthreads();

    if (tid < RES) {
        float t = (float)tid * (1.0f / (RES - 1));
        axx[tid] = slohi[0] + t * (slohi[1] - slohi[0]);
        axy[tid] = slohi[2] + t * (slohi[3] - slohi[2]);
    }
    __syncthreads();

    // ---- Phase 2: sort each (interval,stream) list by py once; window bounds --
    for (int L = w; L < 64; L += 30) {
        const int i  = L >> 1;
        const int bd = L & 1;
        float2 P = sxy[bd * 1024 + i * NC + lane];
        float key = P.y;
        float px  = P.x;
        float rr  = fmaf(P.x, P.x, P.y * P.y);

        // bitonic sort ascending by key (payload px, rr)
#pragma unroll
        for (int k2 = 2; k2 <= 32; k2 <<= 1) {
#pragma unroll
            for (int j = k2 >> 1; j; j >>= 1) {
                float ok  = __shfl_xor_sync(FULL, key, j);
                float opx = __shfl_xor_sync(FULL, px, j);
                float orr = __shfl_xor_sync(FULL, rr, j);
                bool takeMax   = (((lane & j) != 0) == ((lane & k2) == 0));
                bool takeOther = takeMax ? (ok > key) : (ok < key);
                if (takeOther) { key = ok; px = opx; rr = orr; }
            }
        }

        // quad planes: {py0,py1,r0,r1}; px contiguous in sorted order
        int q = lane >> 1, pos = lane & 1;
        qf[L * 64 + q * 4 + pos]     = key;
        qf[L * 64 + q * 4 + 2 + pos] = rr;
        xf[L * 32 + lane]            = px;

        // per-row window via shfl binary search (all lanes participate in shfl)
        float klo = ((lane < RES) ? axy[lane] : 0.0f) - DELTA;
        float khi = klo + 2.0f * DELTA;
        int lo = 0, hi = 0;
#pragma unroll
        for (int st = 16; st; st >>= 1) {
            float v1 = __shfl_sync(FULL, key, lo + st - 1);
            if (v1 < klo) lo += st;
            float v2 = __shfl_sync(FULL, key, hi + st - 1);
            if (v2 <= khi) hi += st;
        }
        if (lane < RES) {
            // round outward to EVEN quad boundaries: supersets are exact, and
            // even alignment enables the 2-quad unrolled eval (float4 px loads)
            int qlo = (lo >> 1) & ~1;
            int qhi = (((hi + 1) >> 1) + 1) & ~1;
            bnd[L * 30 + lane] = qlo | (qhi << 16);
        }
    }
    __syncthreads();

    // ---- Phase 3: eval (no barriers). 4 sets x 240 threads; set = 8 intervals.
    // thread: iy = t>>3 (row), chunk = t&7, columns chunk + 8k (k<4).
    // Quad loop unrolled 2x (even-aligned windows): 32 distances per iteration.
    const int set = tid / SETSZ;
    const int t   = tid % SETSZ;
    const int iy    = t >> 3;
    const int chunk = t & 7;

    const float gy  = axy[iy];
    const ull n2gy2 = pk2(-2.0f * gy, -2.0f * gy);

    ull   n2gx2[4];
    float kg[4];
#pragma unroll
    for (int k = 0; k < 4; k++) {
        int col = chunk + 8 * k;
        float gx = (col < RES) ? axx[col] : 0.0f;
        n2gx2[k] = pk2(-2.0f * gx, -2.0f * gx);
        kg[k]    = KS2 * fmaf(gx, gx, gy * gy);
    }

    float acc[4];
#pragma unroll
    for (int k = 0; k < 4; k++) acc[k] = 0.0f;

#pragma unroll 1
    for (int ii = 0; ii < 8; ii++) {
        const int i  = set * 8 + ii;
        const int Lb = 2 * i, Ld = 2 * i + 1;
        const int wb = bnd[Lb * 30 + iy];
        const int wd = bnd[Ld * 30 + iy];

        float minb[4], mind[4];
#pragma unroll
        for (int k = 0; k < 4; k++) { minb[k] = 1e30f; mind[k] = 1e30f; }

        {
            const float* qp = qf + Lb * 64;
            const float* xp = xf + Lb * 32;
            const int qhi = wb >> 16;
            for (int q = wb & 0xffff; q < qhi; q += 2) {
                float4 Y0 = *(const float4*)(qp + 4 * q);       // {py0,py1,r0,r1}
                float4 Y1 = *(const float4*)(qp + 4 * q + 4);
                float4 X  = *(const float4*)(xp + 2 * q);       // {px0..px3}
                ull T0 = fma2(n2gy2, pk2(Y0.x, Y0.y), pk2(Y0.z, Y0.w));
                ull T1 = fma2(n2gy2, pk2(Y1.x, Y1.y), pk2(Y1.z, Y1.w));
                ull X0 = pk2(X.x, X.y);
                ull X1 = pk2(X.z, X.w);
#pragma unroll
                for (int k = 0; k < 4; k++) {
                    float2 m0 = unpk(fma2(n2gx2[k], X0, T0));
                    float2 m1 = unpk(fma2(n2gx2[k], X1, T1));
                    minb[k] = fminf(minb[k],
                              fminf(fminf(m0.x, m0.y), fminf(m1.x, m1.y)));
                }
            }
        }
        {
            const float* qp = qf + Ld * 64;
            const float* xp = xf + Ld * 32;
            const int qhi = wd >> 16;
            for (int q = wd & 0xffff; q < qhi; q += 2) {
                float4 Y0 = *(const float4*)(qp + 4 * q);
                float4 Y1 = *(const float4*)(qp + 4 * q + 4);
                float4 X  = *(const float4*)(xp + 2 * q);
                ull T0 = fma2(n2gy2, pk2(Y0.x, Y0.y), pk2(Y0.z, Y0.w));
                ull T1 = fma2(n2gy2, pk2(Y1.x, Y1.y), pk2(Y1.z, Y1.w));
                ull X0 = pk2(X.x, X.y);
                ull X1 = pk2(X.z, X.w);
#pragma unroll
                for (int k = 0; k < 4; k++) {
                    float2 m0 = unpk(fma2(n2gx2[k], X0, T0));
                    float2 m1 = unpk(fma2(n2gx2[k], X1, T1));
                    mind[k] = fminf(mind[k],
                              fminf(fminf(m0.x, m0.y), fminf(m1.x, m1.y)));
                }
            }
        }

        const float wv = w2s[i];
#pragma unroll
        for (int k = 0; k < 4; k++) {
            float mm  = fmaxf(minb[k], mind[k]);   // empty window => 1e30 => ex2 -> 0
            float arg = fmaf(KS2, mm, kg[k]);
            acc[k] = fmaf(wv, ex2f(arg), acc[k]);
        }
    }

    // ---- merge sets and store ----
    if (set != 0) {
#pragma unroll
        for (int k = 0; k < 4; k++)
            pacc[(set - 1) * 960 + k * SETSZ + t] = acc[k];
    }
    __syncthreads();
    if (set == 0) {
        float* orow = out + (size_t)s * GRID_PTS;
#pragma unroll
        for (int k = 0; k < 4; k++) {
            int col = chunk + 8 * k;
            if (col < RES) {
                float v = acc[k] + pacc[0 * 960 + k * SETSZ + t]
                                 + pacc[1 * 960 + k * SETSZ + t]
                                 + pacc[2 * 960 + k * SETSZ + t];
                orow[col * RES + iy] = v;
            }
        }
    }
}

extern "C" void kernel_launch(void* const* d_in, const int* in_sizes, int n_in,
                              void* d_out, int out_size) {
    const float* births = (const float*)d_in[0];
    const float* deaths = (const float*)d_in[1];
    float* out = (float*)d_out;
    int S = in_sizes[0] / (NPTS * 2);   // 128 for the reference shapes
    cudaFuncSetAttribute(persim_kernel,
                         cudaFuncAttributeMaxDynamicSharedMemorySize, SMEM_BYTES);
    persim_kernel<<<S, NTHREADS, SMEM_BYTES>>>(births, deaths, out);
}